// round 1
// baseline (speedup 1.0000x reference)
#include <cuda_runtime.h>
#include <math.h>

#define B_ 8
#define C_ 1024
#define T_ 2048
#define I_ 512
#define BN_EPS 1e-5f

// ---------------- static scratch (allocation-free) ----------------
__device__ float g_pg[B_ * I_ * T_];                 // g projection   [B,I,T]
__device__ float g_pt[B_ * I_ * T_];                 // theta proj     [B,I,T]
__device__ float g_pp[B_ * I_ * T_];                 // phi proj       [B,I,T]
__device__ float g_at[(long long)B_ * T_ * T_];      // scores/attn    [B,T,T]
__device__ float g_yv[B_ * I_ * T_];                 // y              [B,I,T]
__device__ float g_mean[C_];
__device__ float g_rstd[C_];

// ---------------- generic tiled fp32 GEMM ----------------
// C[z] = op(A[z]) * op(B[z]) (+ bias[m]) (+ resid[z][m,n])
// op(A): TA=false -> A[m*lda+k]; TA=true -> A[k*lda+m]
// op(B): TB=false -> B[k*ldb+n]; TB=true -> B[n*ldb+k]
#define BM 128
#define BN 128
#define BK 8
#define TM 8
#define TN 8

template <bool TA, bool TB, int EPI>   // EPI: 0=none, 1=+bias, 2=+bias+resid
__global__ __launch_bounds__(256, 2)
void sgemm_kernel(const float* __restrict__ A, const float* __restrict__ Bm,
                  float* __restrict__ Cm,
                  const float* __restrict__ bias, const float* __restrict__ resid,
                  int M, int N, int K, int lda, int ldb, int ldc,
                  long long sA, long long sB, long long sC, long long sR)
{
    __shared__ float As[BK][BM];
    __shared__ float Bs[BK][BN];

    const int tid = threadIdx.x;
    const int bm0 = blockIdx.y * BM;
    const int bn0 = blockIdx.x * BN;

    A  += sA * blockIdx.z;
    Bm += sB * blockIdx.z;
    Cm += sC * blockIdx.z;

    float acc[TM][TN];
#pragma unroll
    for (int i = 0; i < TM; i++)
#pragma unroll
        for (int j = 0; j < TN; j++) acc[i][j] = 0.0f;

    const int row0 = (tid / 16) * TM;
    const int col0 = (tid % 16) * TN;

    for (int k0 = 0; k0 < K; k0 += BK) {
        // load A tile
#pragma unroll
        for (int i = 0; i < (BM * BK) / 256; i++) {
            int idx = tid + i * 256;
            if (TA) {
                int k = idx / BM, m = idx % BM;
                As[k][m] = A[(long long)(k0 + k) * lda + (bm0 + m)];
            } else {
                int m = idx / BK, k = idx % BK;
                As[k][m] = A[(long long)(bm0 + m) * lda + (k0 + k)];
            }
        }
        // load B tile
#pragma unroll
        for (int i = 0; i < (BN * BK) / 256; i++) {
            int idx = tid + i * 256;
            if (TB) {
                int n = idx / BK, k = idx % BK;
                Bs[k][n] = Bm[(long long)(bn0 + n) * ldb + (k0 + k)];
            } else {
                int k = idx / BN, n = idx % BN;
                Bs[k][n] = Bm[(long long)(k0 + k) * ldb + (bn0 + n)];
            }
        }
        __syncthreads();

#pragma unroll
        for (int k = 0; k < BK; k++) {
            float a[TM], b[TN];
#pragma unroll
            for (int i = 0; i < TM; i++) a[i] = As[k][row0 + i];
#pragma unroll
            for (int j = 0; j < TN; j++) b[j] = Bs[k][col0 + j];
#pragma unroll
            for (int i = 0; i < TM; i++)
#pragma unroll
                for (int j = 0; j < TN; j++)
                    acc[i][j] = fmaf(a[i], b[j], acc[i][j]);
        }
        __syncthreads();
    }

    // epilogue
#pragma unroll
    for (int i = 0; i < TM; i++) {
        int m = bm0 + row0 + i;
        float bv = (EPI >= 1) ? bias[m] : 0.0f;
#pragma unroll
        for (int j = 0; j < TN; j++) {
            int n = bn0 + col0 + j;
            float v = acc[i][j] + bv;
            if (EPI == 2) v += resid[sR * blockIdx.z + (long long)m * ldc + n];
            Cm[(long long)m * ldc + n] = v;
        }
    }
}

// ---------------- row softmax over T_=2048 columns ----------------
__global__ __launch_bounds__(256)
void softmax_rows(float* __restrict__ f)
{
    const long long base = (long long)blockIdx.x * T_;
    const int tid = threadIdx.x;
    __shared__ float red[256];

    float v[8];
    float mx = -1e30f;
#pragma unroll
    for (int i = 0; i < 8; i++) {
        v[i] = f[base + tid + i * 256];
        mx = fmaxf(mx, v[i]);
    }
    red[tid] = mx;
    __syncthreads();
#pragma unroll
    for (int s = 128; s > 0; s >>= 1) {
        if (tid < s) red[tid] = fmaxf(red[tid], red[tid + s]);
        __syncthreads();
    }
    const float m = red[0];
    __syncthreads();

    float sum = 0.0f;
#pragma unroll
    for (int i = 0; i < 8; i++) {
        v[i] = __expf(v[i] - m);
        sum += v[i];
    }
    red[tid] = sum;
    __syncthreads();
#pragma unroll
    for (int s = 128; s > 0; s >>= 1) {
        if (tid < s) red[tid] += red[tid + s];
        __syncthreads();
    }
    const float inv = 1.0f / red[0];
#pragma unroll
    for (int i = 0; i < 8; i++)
        f[base + tid + i * 256] = v[i] * inv;
}

// ---------------- batchnorm: stats over (B,T) per channel ----------------
__global__ __launch_bounds__(256)
void bn_stats(const float* __restrict__ s, float* __restrict__ mean,
              float* __restrict__ rstd)
{
    const int c = blockIdx.x;
    const int tid = threadIdx.x;
    float sum = 0.0f, sq = 0.0f;
    for (int idx = tid; idx < B_ * T_; idx += 256) {
        int b = idx >> 11;       // /2048
        int t = idx & (T_ - 1);  // %2048
        float v = s[(long long)b * C_ * T_ + (long long)c * T_ + t];
        sum += v;
        sq = fmaf(v, v, sq);
    }
    __shared__ float r1[256], r2[256];
    r1[tid] = sum; r2[tid] = sq;
    __syncthreads();
#pragma unroll
    for (int st = 128; st > 0; st >>= 1) {
        if (tid < st) { r1[tid] += r1[tid + st]; r2[tid] += r2[tid + st]; }
        __syncthreads();
    }
    if (tid == 0) {
        const float inv_n = 1.0f / (float)(B_ * T_);
        float m = r1[0] * inv_n;
        float var = r2[0] * inv_n - m * m;
        mean[c] = m;
        rstd[c] = rsqrtf(var + BN_EPS);
    }
}

__global__ __launch_bounds__(256)
void bn_apply(float* __restrict__ s, const float* __restrict__ mean,
              const float* __restrict__ rstd, const float* __restrict__ gamma,
              const float* __restrict__ beta)
{
    const int bc = blockIdx.x;            // b*C + c
    const int c = bc & (C_ - 1);          // % 1024
    const long long base = (long long)bc * T_;
    const float m = mean[c], r = rstd[c], g = gamma[c], be = beta[c];
    for (int t = threadIdx.x; t < T_; t += 256)
        s[base + t] = fmaf((s[base + t] - m) * r, g, be);
}

// ---------------- launcher ----------------
extern "C" void kernel_launch(void* const* d_in, const int* in_sizes, int n_in,
                              void* d_out, int out_size)
{
    const float* x     = (const float*)d_in[0];
    const float* g_w   = (const float*)d_in[1];
    const float* g_b   = (const float*)d_in[2];
    const float* th_w  = (const float*)d_in[3];
    const float* th_b  = (const float*)d_in[4];
    const float* ph_w  = (const float*)d_in[5];
    const float* ph_b  = (const float*)d_in[6];
    const float* W_w   = (const float*)d_in[7];
    const float* W_b   = (const float*)d_in[8];
    const float* gamma = (const float*)d_in[9];
    const float* beta  = (const float*)d_in[10];
    float* out = (float*)d_out;

    float *pg, *pt, *pp, *at, *yv, *mean, *rstd;
    cudaGetSymbolAddress((void**)&pg, g_pg);
    cudaGetSymbolAddress((void**)&pt, g_pt);
    cudaGetSymbolAddress((void**)&pp, g_pp);
    cudaGetSymbolAddress((void**)&at, g_at);
    cudaGetSymbolAddress((void**)&yv, g_yv);
    cudaGetSymbolAddress((void**)&mean, g_mean);
    cudaGetSymbolAddress((void**)&rstd, g_rstd);

    const long long sX  = (long long)C_ * T_;   // batch stride of x / s
    const long long sP  = (long long)I_ * T_;   // batch stride of projections / y
    const long long sF  = (long long)T_ * T_;   // batch stride of attn

    dim3 blk(256);

    // 1) projections: P = W[I,C] @ x_b[C,T] + bias    (M=I, N=T, K=C)
    dim3 grd_p(T_ / BN, I_ / BM, B_);
    sgemm_kernel<false, false, 1><<<grd_p, blk>>>(g_w,  x, pg, g_b,  nullptr,
        I_, T_, C_, C_, T_, T_, 0, sX, sP, 0);
    sgemm_kernel<false, false, 1><<<grd_p, blk>>>(th_w, x, pt, th_b, nullptr,
        I_, T_, C_, C_, T_, T_, 0, sX, sP, 0);
    sgemm_kernel<false, false, 1><<<grd_p, blk>>>(ph_w, x, pp, ph_b, nullptr,
        I_, T_, C_, C_, T_, T_, 0, sX, sP, 0);

    // 2) scores: f_b[t,s] = sum_i theta[i,t] * phi[i,s]   (TN: M=T, N=T, K=I)
    dim3 grd_f(T_ / BN, T_ / BM, B_);
    sgemm_kernel<true, false, 0><<<grd_f, blk>>>(pt, pp, at, nullptr, nullptr,
        T_, T_, I_, T_, T_, T_, sP, sP, sF, 0);

    // 3) softmax over last dim
    softmax_rows<<<B_ * T_, blk>>>(at);

    // 4) y_b[i,t] = sum_s g[i,s] * attn[t,s]   (NT: M=I, N=T, K=T)
    dim3 grd_y(T_ / BN, I_ / BM, B_);
    sgemm_kernel<false, true, 0><<<grd_y, blk>>>(pg, at, yv, nullptr, nullptr,
        I_, T_, T_, T_, T_, T_, sP, sF, sP, 0);

    // 5) s = W_w[C,I] @ y_b[I,T] + W_b + x  -> d_out    (M=C, N=T, K=I)
    dim3 grd_o(T_ / BN, C_ / BM, B_);
    sgemm_kernel<false, false, 2><<<grd_o, blk>>>(W_w, yv, out, W_b, x,
        C_, T_, I_, I_, T_, T_, 0, sP, sX, sX);

    // 6) batchnorm stats + apply (in place on d_out)
    bn_stats<<<C_, blk>>>(out, mean, rstd);
    bn_apply<<<B_ * C_, blk>>>(out, mean, rstd, gamma, beta);
}